// round 15
// baseline (speedup 1.0000x reference)
#include <cuda_runtime.h>
#include <cuda_bf16.h>
#include <cuda_fp16.h>
#include <math.h>
#include <stdint.h>

#define NN 50000
#define EE 800000
#define GG 512
#define DD 128

// ---------------- scratch (device globals; no allocations) ----------------
__device__ __half d_Qh[NN * DD];       // fp16 Q table [node*128 + col]
__device__ __half d_KVh[NN * 256];     // fused K/V: [node*256 + (col/4)*8 + col%4 (+4 for V)]
__device__ float d_H[NN * DD];         // layer-0 skip accumulator (fp32)
__device__ __half d_Hh[NN * DD];       // relu(layer-0 out) in fp16 -> GEMM1 input
__device__ float d_GSUM[GG * DD];
__device__ float d_GCNT[GG];
// CSR (by dst)
__device__ int   d_cnt[NN];            // counts, then cursor
__device__ int   d_rowstart[NN + 1];
__device__ int2  d_pedge[EE];          // packed (src, ea-bits)
// decoupled-lookback scan state (reset every call in k_prep)
__device__ int   d_agg[256];
__device__ int   d_incl[256];
__device__ int   d_flag[256];
// pre-converted weights: 8 mats (layer0 q,k,v,skip; layer1 q,k,v,skip), fp16
__device__ uint32_t d_WH[8][8192];     // half2 pairs, [o][pair]

// ---------------- helpers ----------------
__device__ __forceinline__ uint32_t smem_u32(const void* p) {
    uint32_t a;
    asm("{ .reg .u64 t; cvta.to.shared.u64 t, %1; cvt.u32.u64 %0, t; }" : "=r"(a) : "l"(p));
    return a;
}

#define LDSM_X4(r, addr)                                                      \
    asm volatile("ldmatrix.sync.aligned.m8n8.x4.shared.b16 {%0,%1,%2,%3}, [%4];" \
                 : "=r"((r)[0]), "=r"((r)[1]), "=r"((r)[2]), "=r"((r)[3])     \
                 : "r"(addr))

__device__ __forceinline__ void mma16816(float* c, const uint32_t* a,
                                         uint32_t b0, uint32_t b1) {
    asm volatile(
        "mma.sync.aligned.m16n8k16.row.col.f32.f16.f16.f32 "
        "{%0,%1,%2,%3}, {%4,%5,%6,%7}, {%8,%9}, {%0,%1,%2,%3};"
        : "+f"(c[0]), "+f"(c[1]), "+f"(c[2]), "+f"(c[3])
        : "r"(a[0]), "r"(a[1]), "r"(a[2]), "r"(a[3]), "r"(b0), "r"(b1));
}

// ---------------- prep: wconv + zero arrays + scan-flag reset --------------
// blocks [0,256): weight conversion; [256,512): zero cnt/GSUM/GCNT/flags.
// NOTE: histogram must be a SEPARATE launch (zeroing and hist would race
// within one kernel — no inter-block ordering).
__global__ void k_prep(const float* __restrict__ w0, const float* __restrict__ w1,
                       const float* __restrict__ w2, const float* __restrict__ w3,
                       const float* __restrict__ w4, const float* __restrict__ w5,
                       const float* __restrict__ w6, const float* __restrict__ w7,
                       int n) {
    int b = blockIdx.x, t = threadIdx.x;
    if (b < 256) {
        int idx = b * 256 + t;                  // 0..65535
        int m = idx >> 13, p = idx & 8191;
        const float* ws[8] = {w0, w1, w2, w3, w4, w5, w6, w7};
        float2 v = ((const float2*)ws[m])[p];
        __half2 hh = __floats2half2_rn(v.x, v.y);
        d_WH[m][p] = *(uint32_t*)&hh;
    } else {
        int i = (b - 256) * 256 + t;            // 0..65535
        if (i < n) d_cnt[i] = 0;
        if (i < GG * DD) d_GSUM[i] = 0.0f;
        if (i < GG) d_GCNT[i] = 0.0f;
        if (i < 256) d_flag[i] = 0;
    }
}

__global__ void k_hist(const int* __restrict__ dst, int E) {
    int e = blockIdx.x * blockDim.x + threadIdx.x;
    if (e < E) atomicAdd(&d_cnt[dst[e]], 1);
}

// ---------------- single-pass decoupled-lookback scan ----------------------
__global__ void k_scan(int n, int E) {
    __shared__ int wsum[8];
    __shared__ int s_off;
    int b = blockIdx.x, t = threadIdx.x;
    int i = b * 256 + t;
    int v = (i < n) ? d_cnt[i] : 0;
    int lane = t & 31, w = t >> 5;
    int x = v;
#pragma unroll
    for (int o = 1; o < 32; o <<= 1) {
        int u = __shfl_up_sync(0xffffffffu, x, o);
        if (lane >= o) x += u;
    }
    if (lane == 31) wsum[w] = x;
    __syncthreads();
    if (t < 8) {
        int ws = wsum[t];
#pragma unroll
        for (int o = 1; o < 8; o <<= 1) {
            int u = __shfl_up_sync(0x000000ffu, ws, o);
            if (t >= o) ws += u;
        }
        wsum[t] = ws;   // inclusive warp sums
    }
    __syncthreads();
    int excl = x - v + (w > 0 ? wsum[w - 1] : 0);
    int total = wsum[7];

    if (t == 0) {
        d_agg[b] = total;
        __threadfence();
        atomicExch(&d_flag[b], 1);
        int running = 0;
        int j = b - 1;
        while (j >= 0) {
            int f;
            do { f = atomicAdd(&d_flag[j], 0); } while (f == 0);
            if (f == 2) { running += atomicAdd(&d_incl[j], 0); break; }
            running += atomicAdd(&d_agg[j], 0);
            j--;
        }
        d_incl[b] = running + total;
        __threadfence();
        atomicExch(&d_flag[b], 2);
        s_off = running;
    }
    __syncthreads();
    int off = s_off;
    if (i < n) {
        int val = excl + off;
        d_rowstart[i] = val;
        d_cnt[i] = val;      // cursor for k_fill
    }
    if (i == 0) d_rowstart[n] = E;
}

__global__ void k_fill(const int* __restrict__ src, const int* __restrict__ dst,
                       const float* __restrict__ ea, int E) {
    int e = blockIdx.x * blockDim.x + threadIdx.x;
    if (e >= E) return;
    int d = dst[e];
    int pos = atomicAdd(&d_cnt[d], 1);
    d_pedge[pos] = make_int2(src[e], __float_as_int(ea[e]));
}

// ---------------- tensor-core GEMM (fp16), single W buffer, 2 CTA/SM -------
#define ROWB 272
#define SA_OFF 0
#define SW_OFF (SA_OFF + 64 * ROWB)      // 17408
#define SBIAS  (SW_OFF + 128 * ROWB)     // 52224
#define GSM_TOTAL (SBIAS + 2048)         // 54272

__global__ void __launch_bounds__(256, 2)
k_gemm_mma(const float* __restrict__ Xext, int use_ext, int use_h16, int n,
           int wbase,
           const float* __restrict__ bq, const float* __restrict__ bk,
           const float* __restrict__ bv, const float* __restrict__ bsk,
           float* __restrict__ Yskip) {
    extern __shared__ char smem[];
    const uint32_t sb = smem_u32(smem);
    const int tid = threadIdx.x;
    const int wid = tid >> 5;
    const int lane = tid & 31;
    const int row0 = blockIdx.x * 64;
    float* s_bias = (float*)(smem + SBIAS);

    if (tid < 128) {
        s_bias[tid]       = bq[tid];
        s_bias[128 + tid] = bk[tid];
        s_bias[256 + tid] = bv[tid];
        s_bias[384 + tid] = bsk[tid];
    }

    // ---- A fill (64 rows x 128 cols fp16) ----
    if (use_h16) {
        for (int idx = tid; idx < 64 * 32; idx += 256) {
            int r = idx >> 5, c = idx & 31;
            int row = row0 + r;
            uint2 uh = make_uint2(0u, 0u);
            if (row < n) uh = ((const uint2*)(d_Hh + (long)row * 128))[c];
            *(uint2*)(smem + SA_OFF + r * ROWB + c * 8) = uh;
        }
    } else {
        for (int idx = tid; idx < 64 * 32; idx += 256) {
            int r = idx >> 5, c = idx & 31;
            int row = row0 + r;
            float4 v = make_float4(0.f, 0.f, 0.f, 0.f);
            if (row < n) v = ((const float4*)Xext)[(long)row * 32 + c];
            __half2 h01 = __floats2half2_rn(v.x, v.y);
            __half2 h23 = __floats2half2_rn(v.z, v.w);
            uint2 uh; uh.x = *(uint32_t*)&h01; uh.y = *(uint32_t*)&h23;
            *(uint2*)(smem + SA_OFF + r * ROWB + c * 8) = uh;
        }
    }
    __syncthreads();

    const int wm = wid & 1;                 // row half (32 rows)
    const int wn = wid >> 1;                // col group (32 cols)
    const int a_row = wm * 32 + (lane & 15);
    const int a_colb = (lane >> 4) * 16;
    const int b_row_in_q = ((lane >> 4) & 1) * 8 + (lane & 7);
    const int b_colb = ((lane >> 3) & 1) * 16;

    // ---- hoist A fragments into registers (loaded ONCE, reused for 4 mats) ----
    uint32_t afr[8][2][4];
#pragma unroll
    for (int ks = 0; ks < 8; ks++) {
        uint32_t aaddr = sb + SA_OFF + a_row * ROWB + ks * 32 + a_colb;
        LDSM_X4(afr[ks][0], aaddr);
        LDSM_X4(afr[ks][1], aaddr + 16 * ROWB);
    }

    for (int m = 0; m < 4; m++) {
        // ---- W fill: plain fp16 copy from pre-converted globals ----
        const uint32_t* WH = d_WH[wbase + m];
        for (int idx = tid; idx < 2048; idx += 256) {
            int o = idx >> 4, c = idx & 15;
            uint4 h = ((const uint4*)WH)[idx];
            *(uint4*)(smem + SW_OFF + o * ROWB + c * 16) = h;
        }
        __syncthreads();

        float acc[2][4][4];
#pragma unroll
        for (int i = 0; i < 2; i++)
#pragma unroll
            for (int j = 0; j < 4; j++)
#pragma unroll
                for (int c = 0; c < 4; c++) acc[i][j][c] = 0.f;

        uint32_t Bb = sb + SW_OFF;
#pragma unroll
        for (int ks = 0; ks < 8; ks++) {
#pragma unroll
            for (int q = 0; q < 2; q++) {
                uint32_t b[4];
                uint32_t baddr = Bb + (wn * 32 + q * 16 + b_row_in_q) * ROWB
                                 + ks * 32 + b_colb;
                LDSM_X4(b, baddr);
                mma16816(acc[0][2 * q],     afr[ks][0], b[0], b[1]);
                mma16816(acc[0][2 * q + 1], afr[ks][0], b[2], b[3]);
                mma16816(acc[1][2 * q],     afr[ks][1], b[0], b[1]);
                mma16816(acc[1][2 * q + 1], afr[ks][1], b[2], b[3]);
            }
        }

        // ---- epilogue ----
#pragma unroll
        for (int tm = 0; tm < 2; tm++) {
#pragma unroll
            for (int tn = 0; tn < 4; tn++) {
                int col = wn * 32 + tn * 8 + (lane & 3) * 2;
                float bx = s_bias[m * 128 + col];
                float by = s_bias[m * 128 + col + 1];
                int r1 = row0 + wm * 32 + tm * 16 + (lane >> 2);
                int r2 = r1 + 8;
                float v1x = acc[tm][tn][0] + bx, v1y = acc[tm][tn][1] + by;
                float v2x = acc[tm][tn][2] + bx, v2y = acc[tm][tn][3] + by;
                if (m == 0) {
                    if (r1 < n) {
                        __half2 h1 = __floats2half2_rn(v1x, v1y);
                        *(__half2*)&d_Qh[(long)r1 * 128 + col] = h1;
                    }
                    if (r2 < n) {
                        __half2 h2 = __floats2half2_rn(v2x, v2y);
                        *(__half2*)&d_Qh[(long)r2 * 128 + col] = h2;
                    }
                } else if (m < 3) {
                    int kvoff = ((col >> 2) << 3) + (col & 3) + ((m == 2) ? 4 : 0);
                    if (r1 < n) {
                        __half2 h1 = __floats2half2_rn(v1x, v1y);
                        *(__half2*)&d_KVh[(long)r1 * 256 + kvoff] = h1;
                    }
                    if (r2 < n) {
                        __half2 h2 = __floats2half2_rn(v2x, v2y);
                        *(__half2*)&d_KVh[(long)r2 * 256 + kvoff] = h2;
                    }
                } else {
                    float* Y = Yskip ? Yskip : d_H;
                    if (r1 < n) *(float2*)&Y[(long)r1 * 128 + col] = make_float2(v1x, v1y);
                    if (r2 < n) *(float2*)&Y[(long)r2 * 128 + col] = make_float2(v2x, v2y);
                }
            }
        }
        __syncthreads();
    }
}

// ---------------- fused edge kernel: single-pass softmax + aggregate -------
__global__ void k_edge_fused(const float* __restrict__ We, int n,
                             int use_dout, float* __restrict__ dout,
                             const int* __restrict__ batch, int do_pool) {
    int node = blockIdx.x * 8 + (threadIdx.x >> 5);
    if (node >= n) return;
    int lane = threadIdx.x & 31;

    float4 we4 = __ldg((const float4*)We + lane);
    uint2 qq = *((const uint2*)&d_Qh[(long)node * DD] + lane);
    float2 qa = __half22float2(*(half2*)&qq.x);
    float2 qb = __half22float2(*(half2*)&qq.y);
    int p0 = d_rowstart[node];
    int p1 = d_rowstart[node + 1];

    float ax = 0.f, ay = 0.f, az = 0.f, aw = 0.f;
    float den = 0.f;

    int2 pe = make_int2(0, 0);
    uint4 kv = make_uint4(0u, 0u, 0u, 0u);
    if (p0 < p1) {
        pe = __ldg(&d_pedge[p0]);
        kv = __ldg((const uint4*)(d_KVh + (long)pe.x * 256) + lane);
    }

    for (int p = p0; p < p1; p++) {
        float cea = __int_as_float(pe.y);
        float2 ka = __half22float2(*(half2*)&kv.x);
        float2 kb = __half22float2(*(half2*)&kv.y);
        float2 va = __half22float2(*(half2*)&kv.z);
        float2 vb = __half22float2(*(half2*)&kv.w);
        float ex_x = va.x + cea * we4.x;
        float ex_y = va.y + cea * we4.y;
        float ex_z = vb.x + cea * we4.z;
        float ex_w = vb.y + cea * we4.w;
        float t = qa.x * (ka.x + cea * we4.x) + qa.y * (ka.y + cea * we4.y) +
                  qb.x * (kb.x + cea * we4.z) + qb.y * (kb.y + cea * we4.w);

        if (p + 1 < p1) {
            pe = __ldg(&d_pedge[p + 1]);
            kv = __ldg((const uint4*)(d_KVh + (long)pe.x * 256) + lane);
        }

        t += __shfl_xor_sync(0xffffffffu, t, 8);
        t += __shfl_xor_sync(0xffffffffu, t, 4);
        t += __shfl_xor_sync(0xffffffffu, t, 2);
        t += __shfl_xor_sync(0xffffffffu, t, 1);
        float ex = __expf(t * 0.125f);          // no-max softmax (shift-invariant)
        ax += ex * ex_x;
        ay += ex * ex_y;
        az += ex * ex_z;
        aw += ex * ex_w;
        den += ex;
    }

    float inv = 1.f / (den + 1e-16f);
    if (use_dout) {
        float4* op = (float4*)&dout[(long)node * DD] + lane;
        float4 o = *op;                          // skip written by GEMM
        o.x += ax * inv; o.y += ay * inv; o.z += az * inv; o.w += aw * inv;
        *op = o;
        if (do_pool) {
            int g = __ldg(&batch[node]);
            float* pp = &d_GSUM[(long)g * DD + lane * 4];
            asm volatile("red.global.add.v4.f32 [%0], {%1,%2,%3,%4};"
                         :: "l"(pp), "f"(o.x), "f"(o.y), "f"(o.z), "f"(o.w)
                         : "memory");
            if (lane == 0) atomicAdd(&d_GCNT[g], 1.0f);
        }
    } else {
        // layer 0: relu + fp16 store to d_Hh
        float4 o = *((const float4*)&d_H[(long)node * DD] + lane);  // skip
        o.x = fmaxf(o.x + ax * inv, 0.f);
        o.y = fmaxf(o.y + ay * inv, 0.f);
        o.z = fmaxf(o.z + az * inv, 0.f);
        o.w = fmaxf(o.w + aw * inv, 0.f);
        __half2 h01 = __floats2half2_rn(o.x, o.y);
        __half2 h23 = __floats2half2_rn(o.z, o.w);
        uint2 u; u.x = *(uint32_t*)&h01; u.y = *(uint32_t*)&h23;
        *((uint2*)&d_Hh[(long)node * DD] + lane) = u;
    }
}

// ---------------- MLP head ----------------
__global__ void k_mlp(const float* __restrict__ W1, const float* __restrict__ b1,
                      const float* __restrict__ W2, const float* __restrict__ b2,
                      const float* __restrict__ W3, const float* __restrict__ b3,
                      float* __restrict__ out, int n_nodes) {
    __shared__ float g[128];
    __shared__ float h1[64];
    __shared__ float h2[32];
    int gr = blockIdx.x;
    int t = threadIdx.x;
    float cnt = fmaxf(d_GCNT[gr], 1.0f);
    if (t < 128) g[t] = d_GSUM[gr * 128 + t] / cnt;
    __syncthreads();
    if (t < 64) {
        float s = b1[t];
        for (int k = 0; k < 128; k++) s += W1[t * 128 + k] * g[k];
        h1[t] = fmaxf(s, 0.0f);
    }
    __syncthreads();
    if (t < 32) {
        float s = b2[t];
        for (int k = 0; k < 64; k++) s += W2[t * 64 + k] * h1[k];
        h2[t] = fmaxf(s, 0.0f);
    }
    __syncthreads();
    if (t < 16) {
        float s = b3[t];
        for (int k = 0; k < 32; k++) s += W3[t * 32 + k] * h2[k];
        out[(long)n_nodes * 128 + gr * 16 + t] = s;
    }
}

// ---------------- launcher ----------------
extern "C" void kernel_launch(void* const* d_in, const int* in_sizes, int n_in,
                              void* d_out, int out_size) {
    const float* x      = (const float*)d_in[0];
    const int*   ei     = (const int*)d_in[1];
    const int*   batch  = (const int*)d_in[2];
    const float* eattr  = (const float*)d_in[3];

    const float* Wq0 = (const float*)d_in[4];
    const float* bq0 = (const float*)d_in[5];
    const float* Wk0 = (const float*)d_in[6];
    const float* bk0 = (const float*)d_in[7];
    const float* Wv0 = (const float*)d_in[8];
    const float* bv0 = (const float*)d_in[9];
    const float* We0 = (const float*)d_in[10];
    const float* Ws0 = (const float*)d_in[11];
    const float* bs0 = (const float*)d_in[12];

    const float* Wq1 = (const float*)d_in[13];
    const float* bq1 = (const float*)d_in[14];
    const float* Wk1 = (const float*)d_in[15];
    const float* bk1 = (const float*)d_in[16];
    const float* Wv1 = (const float*)d_in[17];
    const float* bv1 = (const float*)d_in[18];
    const float* We1 = (const float*)d_in[19];
    const float* Ws1 = (const float*)d_in[20];
    const float* bs1 = (const float*)d_in[21];

    const float* W1 = (const float*)d_in[22];
    const float* b1 = (const float*)d_in[23];
    const float* W2 = (const float*)d_in[24];
    const float* b2 = (const float*)d_in[25];
    const float* W3 = (const float*)d_in[26];
    const float* b3 = (const float*)d_in[27];

    int n = in_sizes[2];        // num nodes
    int E = in_sizes[3];        // num edges
    float* out = (float*)d_out;

    cudaFuncSetAttribute(k_gemm_mma, cudaFuncAttributeMaxDynamicSharedMemorySize, GSM_TOTAL);

    const int* src = ei;
    const int* dst = ei + E;

    int gb = (n + 63) / 64;
    int nb8 = (n + 7) / 8;
    int snb = (n + 255) / 256;       // scan blocks (<=256 required)

    // 9 launches total (gemm0 at index 3 for ncu sampling)
    k_prep<<<512, 256>>>(Wq0, Wk0, Wv0, Ws0, Wq1, Wk1, Wv1, Ws1, n);
    k_hist<<<(E + 255) / 256, 256>>>(dst, E);
    k_scan<<<snb, 256>>>(n, E);
    k_gemm_mma<<<gb, 256, GSM_TOTAL>>>(x, 1, 0, n, 0, bq0, bk0, bv0, bs0, nullptr);
    k_fill<<<(E + 255) / 256, 256>>>(src, dst, eattr, E);

    // ---- layer 0 edges (writes relu'd fp16 H) ----
    k_edge_fused<<<nb8, 256>>>(We0, n, 0, nullptr, nullptr, 0);

    // ---- layer 1 (A = d_Hh copy; skip+messages -> d_out; pool fused) ----
    k_gemm_mma<<<gb, 256, GSM_TOTAL>>>(nullptr, 0, 1, n, 4, bq1, bk1, bv1, bs1, out);
    k_edge_fused<<<nb8, 256>>>(We1, n, 1, out, batch, 1);

    // ---- MLP head ----
    k_mlp<<<GG, 128>>>(W1, b1, W2, b2, W3, b3, out, n);
}

// round 16
// speedup vs baseline: 1.0607x; 1.0607x over previous
#include <cuda_runtime.h>
#include <cuda_bf16.h>
#include <cuda_fp16.h>
#include <math.h>
#include <stdint.h>

#define NN 50000
#define EE 800000
#define GG 512
#define DD 128

// ---------------- scratch (device globals; no allocations) ----------------
__device__ __half d_Qh[NN * DD];       // fp16 Q table [node*128 + col]
__device__ __half d_KVh[NN * 256];     // fused K/V: [node*256 + (col/4)*8 + col%4 (+4 for V)]
__device__ float d_H[NN * DD];         // layer-0 skip accumulator (fp32)
__device__ __half d_Hh[NN * DD];       // relu(layer-0 out) in fp16 -> GEMM1 input
__device__ float d_GSUM[GG * DD];
__device__ float d_GCNT[GG];
// CSR (by dst)
__device__ int   d_cnt[NN];            // counts, then cursor
__device__ int   d_rowstart[NN + 1];
__device__ int   d_bsum[256];          // block sums for hierarchical scan
__device__ int2  d_pedge[EE];          // packed (src, ea-bits)
// pre-converted weights: 8 mats (layer0 q,k,v,skip; layer1 q,k,v,skip), fp16
__device__ uint32_t d_WH[8][8192];     // half2 pairs, [o][pair]

// ---------------- helpers ----------------
__device__ __forceinline__ uint32_t smem_u32(const void* p) {
    uint32_t a;
    asm("{ .reg .u64 t; cvta.to.shared.u64 t, %1; cvt.u32.u64 %0, t; }" : "=r"(a) : "l"(p));
    return a;
}

#define LDSM_X4(r, addr)                                                      \
    asm volatile("ldmatrix.sync.aligned.m8n8.x4.shared.b16 {%0,%1,%2,%3}, [%4];" \
                 : "=r"((r)[0]), "=r"((r)[1]), "=r"((r)[2]), "=r"((r)[3])     \
                 : "r"(addr))

__device__ __forceinline__ void mma16816(float* c, const uint32_t* a,
                                         uint32_t b0, uint32_t b1) {
    asm volatile(
        "mma.sync.aligned.m16n8k16.row.col.f32.f16.f16.f32 "
        "{%0,%1,%2,%3}, {%4,%5,%6,%7}, {%8,%9}, {%0,%1,%2,%3};"
        : "+f"(c[0]), "+f"(c[1]), "+f"(c[2]), "+f"(c[3])
        : "r"(a[0]), "r"(a[1]), "r"(a[2]), "r"(a[3]), "r"(b0), "r"(b1));
}

// ---------------- prep: wconv + zero arrays (dependency-safe fusion) -------
__global__ void k_prep(const float* __restrict__ w0, const float* __restrict__ w1,
                       const float* __restrict__ w2, const float* __restrict__ w3,
                       const float* __restrict__ w4, const float* __restrict__ w5,
                       const float* __restrict__ w6, const float* __restrict__ w7,
                       int n) {
    int b = blockIdx.x, t = threadIdx.x;
    if (b < 256) {
        int idx = b * 256 + t;                  // 0..65535
        int m = idx >> 13, p = idx & 8191;
        const float* ws[8] = {w0, w1, w2, w3, w4, w5, w6, w7};
        float2 v = ((const float2*)ws[m])[p];
        __half2 hh = __floats2half2_rn(v.x, v.y);
        d_WH[m][p] = *(uint32_t*)&hh;
    } else {
        int i = (b - 256) * 256 + t;            // 0..65535
        if (i < n) d_cnt[i] = 0;
        if (i < GG * DD) d_GSUM[i] = 0.0f;
        if (i < GG) d_GCNT[i] = 0.0f;
    }
}

__global__ void k_hist(const int* __restrict__ dst, int E) {
    int e = blockIdx.x * blockDim.x + threadIdx.x;
    if (e < E) atomicAdd(&d_cnt[dst[e]], 1);
}

// hierarchical scan, phase 1: per-block (256-wide) exclusive scan, coalesced
__global__ void k_scan1(int n) {
    __shared__ int wsum[8];
    int t = threadIdx.x;
    int i = blockIdx.x * 256 + t;
    int v = (i < n) ? d_cnt[i] : 0;
    int lane = t & 31, w = t >> 5;
    int x = v;
#pragma unroll
    for (int o = 1; o < 32; o <<= 1) {
        int u = __shfl_up_sync(0xffffffffu, x, o);
        if (lane >= o) x += u;
    }
    if (lane == 31) wsum[w] = x;
    __syncthreads();
    if (t < 8) {
        int ws = wsum[t];
#pragma unroll
        for (int o = 1; o < 8; o <<= 1) {
            int u = __shfl_up_sync(0x000000ffu, ws, o);
            if (t >= o) ws += u;
        }
        wsum[t] = ws;   // inclusive
    }
    __syncthreads();
    int excl = x - v + (w > 0 ? wsum[w - 1] : 0);
    if (i < n) d_rowstart[i] = excl;          // local prefix
    if (t == 255) d_bsum[blockIdx.x] = excl + v;  // block total
}

// phase 2: exclusive scan of block sums (nb <= 256), 1 block
__global__ void k_scan2(int nb) {
    __shared__ int wsum[8];
    int t = threadIdx.x;
    int v = (t < nb) ? d_bsum[t] : 0;
    int lane = t & 31, w = t >> 5;
    int x = v;
#pragma unroll
    for (int o = 1; o < 32; o <<= 1) {
        int u = __shfl_up_sync(0xffffffffu, x, o);
        if (lane >= o) x += u;
    }
    if (lane == 31) wsum[w] = x;
    __syncthreads();
    if (t < 8) {
        int ws = wsum[t];
#pragma unroll
        for (int o = 1; o < 8; o <<= 1) {
            int u = __shfl_up_sync(0x000000ffu, ws, o);
            if (t >= o) ws += u;
        }
        wsum[t] = ws;
    }
    __syncthreads();
    int excl = x - v + (w > 0 ? wsum[w - 1] : 0);
    if (t < nb) d_bsum[t] = excl;
}

// phase 3: add block offsets; init cursor; rowstart[n] = E
__global__ void k_scan3(int n, int E) {
    int i = blockIdx.x * 256 + threadIdx.x;
    if (i < n) {
        int v = d_rowstart[i] + d_bsum[blockIdx.x];
        d_rowstart[i] = v;
        d_cnt[i] = v;      // cursor for k_fill
    }
    if (i == 0) d_rowstart[n] = E;
}

__global__ void k_fill(const int* __restrict__ src, const int* __restrict__ dst,
                       const float* __restrict__ ea, int E) {
    int e = blockIdx.x * blockDim.x + threadIdx.x;
    if (e >= E) return;
    int d = dst[e];
    int pos = atomicAdd(&d_cnt[d], 1);
    d_pedge[pos] = make_int2(src[e], __float_as_int(ea[e]));
}

// ---------------- tensor-core GEMM (fp16), single W buffer, 2 CTA/SM -------
#define ROWB 272
#define SA_OFF 0
#define SW_OFF (SA_OFF + 64 * ROWB)      // 17408
#define SBIAS  (SW_OFF + 128 * ROWB)     // 52224
#define GSM_TOTAL (SBIAS + 2048)         // 54272

__global__ void __launch_bounds__(256, 2)
k_gemm_mma(const float* __restrict__ Xext, int use_ext, int use_h16, int n,
           int wbase,
           const float* __restrict__ bq, const float* __restrict__ bk,
           const float* __restrict__ bv, const float* __restrict__ bsk,
           float* __restrict__ Yskip) {
    extern __shared__ char smem[];
    const uint32_t sb = smem_u32(smem);
    const int tid = threadIdx.x;
    const int wid = tid >> 5;
    const int lane = tid & 31;
    const int row0 = blockIdx.x * 64;
    float* s_bias = (float*)(smem + SBIAS);

    if (tid < 128) {
        s_bias[tid]       = bq[tid];
        s_bias[128 + tid] = bk[tid];
        s_bias[256 + tid] = bv[tid];
        s_bias[384 + tid] = bsk[tid];
    }

    // ---- A fill (64 rows x 128 cols fp16) ----
    if (use_h16) {
        for (int idx = tid; idx < 64 * 32; idx += 256) {
            int r = idx >> 5, c = idx & 31;
            int row = row0 + r;
            uint2 uh = make_uint2(0u, 0u);
            if (row < n) uh = ((const uint2*)(d_Hh + (long)row * 128))[c];
            *(uint2*)(smem + SA_OFF + r * ROWB + c * 8) = uh;
        }
    } else {
        for (int idx = tid; idx < 64 * 32; idx += 256) {
            int r = idx >> 5, c = idx & 31;
            int row = row0 + r;
            float4 v = make_float4(0.f, 0.f, 0.f, 0.f);
            if (row < n) v = ((const float4*)Xext)[(long)row * 32 + c];
            __half2 h01 = __floats2half2_rn(v.x, v.y);
            __half2 h23 = __floats2half2_rn(v.z, v.w);
            uint2 uh; uh.x = *(uint32_t*)&h01; uh.y = *(uint32_t*)&h23;
            *(uint2*)(smem + SA_OFF + r * ROWB + c * 8) = uh;
        }
    }
    __syncthreads();

    const int wm = wid & 1;                 // row half (32 rows)
    const int wn = wid >> 1;                // col group (32 cols)
    const int a_row = wm * 32 + (lane & 15);
    const int a_colb = (lane >> 4) * 16;
    const int b_row_in_q = ((lane >> 4) & 1) * 8 + (lane & 7);
    const int b_colb = ((lane >> 3) & 1) * 16;

    // ---- hoist A fragments into registers (loaded ONCE, reused for 4 mats) ----
    uint32_t afr[8][2][4];
#pragma unroll
    for (int ks = 0; ks < 8; ks++) {
        uint32_t aaddr = sb + SA_OFF + a_row * ROWB + ks * 32 + a_colb;
        LDSM_X4(afr[ks][0], aaddr);
        LDSM_X4(afr[ks][1], aaddr + 16 * ROWB);
    }

    for (int m = 0; m < 4; m++) {
        // ---- W fill: plain fp16 copy from pre-converted globals ----
        const uint32_t* WH = d_WH[wbase + m];
        for (int idx = tid; idx < 2048; idx += 256) {
            int o = idx >> 4, c = idx & 15;
            uint4 h = ((const uint4*)WH)[idx];
            *(uint4*)(smem + SW_OFF + o * ROWB + c * 16) = h;
        }
        __syncthreads();

        float acc[2][4][4];
#pragma unroll
        for (int i = 0; i < 2; i++)
#pragma unroll
            for (int j = 0; j < 4; j++)
#pragma unroll
                for (int c = 0; c < 4; c++) acc[i][j][c] = 0.f;

        uint32_t Bb = sb + SW_OFF;
#pragma unroll
        for (int ks = 0; ks < 8; ks++) {
#pragma unroll
            for (int q = 0; q < 2; q++) {
                uint32_t b[4];
                uint32_t baddr = Bb + (wn * 32 + q * 16 + b_row_in_q) * ROWB
                                 + ks * 32 + b_colb;
                LDSM_X4(b, baddr);
                mma16816(acc[0][2 * q],     afr[ks][0], b[0], b[1]);
                mma16816(acc[0][2 * q + 1], afr[ks][0], b[2], b[3]);
                mma16816(acc[1][2 * q],     afr[ks][1], b[0], b[1]);
                mma16816(acc[1][2 * q + 1], afr[ks][1], b[2], b[3]);
            }
        }

        // ---- epilogue ----
#pragma unroll
        for (int tm = 0; tm < 2; tm++) {
#pragma unroll
            for (int tn = 0; tn < 4; tn++) {
                int col = wn * 32 + tn * 8 + (lane & 3) * 2;
                float bx = s_bias[m * 128 + col];
                float by = s_bias[m * 128 + col + 1];
                int r1 = row0 + wm * 32 + tm * 16 + (lane >> 2);
                int r2 = r1 + 8;
                float v1x = acc[tm][tn][0] + bx, v1y = acc[tm][tn][1] + by;
                float v2x = acc[tm][tn][2] + bx, v2y = acc[tm][tn][3] + by;
                if (m == 0) {
                    if (r1 < n) {
                        __half2 h1 = __floats2half2_rn(v1x, v1y);
                        *(__half2*)&d_Qh[(long)r1 * 128 + col] = h1;
                    }
                    if (r2 < n) {
                        __half2 h2 = __floats2half2_rn(v2x, v2y);
                        *(__half2*)&d_Qh[(long)r2 * 128 + col] = h2;
                    }
                } else if (m < 3) {
                    int kvoff = ((col >> 2) << 3) + (col & 3) + ((m == 2) ? 4 : 0);
                    if (r1 < n) {
                        __half2 h1 = __floats2half2_rn(v1x, v1y);
                        *(__half2*)&d_KVh[(long)r1 * 256 + kvoff] = h1;
                    }
                    if (r2 < n) {
                        __half2 h2 = __floats2half2_rn(v2x, v2y);
                        *(__half2*)&d_KVh[(long)r2 * 256 + kvoff] = h2;
                    }
                } else {
                    float* Y = Yskip ? Yskip : d_H;
                    if (r1 < n) *(float2*)&Y[(long)r1 * 128 + col] = make_float2(v1x, v1y);
                    if (r2 < n) *(float2*)&Y[(long)r2 * 128 + col] = make_float2(v2x, v2y);
                }
            }
        }
        __syncthreads();
    }
}

// ---------------- fused edge kernel: single-pass softmax + aggregate -------
__global__ void k_edge_fused(const float* __restrict__ We, int n,
                             int use_dout, float* __restrict__ dout,
                             const int* __restrict__ batch, int do_pool) {
    int node = blockIdx.x * 8 + (threadIdx.x >> 5);
    if (node >= n) return;
    int lane = threadIdx.x & 31;

    float4 we4 = __ldg((const float4*)We + lane);
    uint2 qq = *((const uint2*)&d_Qh[(long)node * DD] + lane);
    float2 qa = __half22float2(*(half2*)&qq.x);
    float2 qb = __half22float2(*(half2*)&qq.y);
    int p0 = d_rowstart[node];
    int p1 = d_rowstart[node + 1];

    float ax = 0.f, ay = 0.f, az = 0.f, aw = 0.f;
    float den = 0.f;

    int2 pe = make_int2(0, 0);
    uint4 kv = make_uint4(0u, 0u, 0u, 0u);
    if (p0 < p1) {
        pe = __ldg(&d_pedge[p0]);
        kv = __ldg((const uint4*)(d_KVh + (long)pe.x * 256) + lane);
    }

    for (int p = p0; p < p1; p++) {
        float cea = __int_as_float(pe.y);
        float2 ka = __half22float2(*(half2*)&kv.x);
        float2 kb = __half22float2(*(half2*)&kv.y);
        float2 va = __half22float2(*(half2*)&kv.z);
        float2 vb = __half22float2(*(half2*)&kv.w);
        float ex_x = va.x + cea * we4.x;
        float ex_y = va.y + cea * we4.y;
        float ex_z = vb.x + cea * we4.z;
        float ex_w = vb.y + cea * we4.w;
        float t = qa.x * (ka.x + cea * we4.x) + qa.y * (ka.y + cea * we4.y) +
                  qb.x * (kb.x + cea * we4.z) + qb.y * (kb.y + cea * we4.w);

        if (p + 1 < p1) {
            pe = __ldg(&d_pedge[p + 1]);
            kv = __ldg((const uint4*)(d_KVh + (long)pe.x * 256) + lane);
        }

        t += __shfl_xor_sync(0xffffffffu, t, 8);
        t += __shfl_xor_sync(0xffffffffu, t, 4);
        t += __shfl_xor_sync(0xffffffffu, t, 2);
        t += __shfl_xor_sync(0xffffffffu, t, 1);
        float ex = __expf(t * 0.125f);          // no-max softmax (shift-invariant)
        ax += ex * ex_x;
        ay += ex * ex_y;
        az += ex * ex_z;
        aw += ex * ex_w;
        den += ex;
    }

    float inv = 1.f / (den + 1e-16f);
    if (use_dout) {
        float4* op = (float4*)&dout[(long)node * DD] + lane;
        float4 o = *op;                          // skip written by GEMM
        o.x += ax * inv; o.y += ay * inv; o.z += az * inv; o.w += aw * inv;
        *op = o;
        if (do_pool) {
            int g = __ldg(&batch[node]);
            float* pp = &d_GSUM[(long)g * DD + lane * 4];
            asm volatile("red.global.add.v4.f32 [%0], {%1,%2,%3,%4};"
                         :: "l"(pp), "f"(o.x), "f"(o.y), "f"(o.z), "f"(o.w)
                         : "memory");
            if (lane == 0) atomicAdd(&d_GCNT[g], 1.0f);
        }
    } else {
        // layer 0: relu + fp16 store to d_Hh
        float4 o = *((const float4*)&d_H[(long)node * DD] + lane);  // skip
        o.x = fmaxf(o.x + ax * inv, 0.f);
        o.y = fmaxf(o.y + ay * inv, 0.f);
        o.z = fmaxf(o.z + az * inv, 0.f);
        o.w = fmaxf(o.w + aw * inv, 0.f);
        __half2 h01 = __floats2half2_rn(o.x, o.y);
        __half2 h23 = __floats2half2_rn(o.z, o.w);
        uint2 u; u.x = *(uint32_t*)&h01; u.y = *(uint32_t*)&h23;
        *((uint2*)&d_Hh[(long)node * DD] + lane) = u;
    }
}

// ---------------- MLP head ----------------
__global__ void k_mlp(const float* __restrict__ W1, const float* __restrict__ b1,
                      const float* __restrict__ W2, const float* __restrict__ b2,
                      const float* __restrict__ W3, const float* __restrict__ b3,
                      float* __restrict__ out, int n_nodes) {
    __shared__ float g[128];
    __shared__ float h1[64];
    __shared__ float h2[32];
    int gr = blockIdx.x;
    int t = threadIdx.x;
    float cnt = fmaxf(d_GCNT[gr], 1.0f);
    if (t < 128) g[t] = d_GSUM[gr * 128 + t] / cnt;
    __syncthreads();
    if (t < 64) {
        float s = b1[t];
        for (int k = 0; k < 128; k++) s += W1[t * 128 + k] * g[k];
        h1[t] = fmaxf(s, 0.0f);
    }
    __syncthreads();
    if (t < 32) {
        float s = b2[t];
        for (int k = 0; k < 64; k++) s += W2[t * 64 + k] * h1[k];
        h2[t] = fmaxf(s, 0.0f);
    }
    __syncthreads();
    if (t < 16) {
        float s = b3[t];
        for (int k = 0; k < 32; k++) s += W3[t * 32 + k] * h2[k];
        out[(long)n_nodes * 128 + gr * 16 + t] = s;
    }
}

// ---------------- launcher ----------------
extern "C" void kernel_launch(void* const* d_in, const int* in_sizes, int n_in,
                              void* d_out, int out_size) {
    const float* x      = (const float*)d_in[0];
    const int*   ei     = (const int*)d_in[1];
    const int*   batch  = (const int*)d_in[2];
    const float* eattr  = (const float*)d_in[3];

    const float* Wq0 = (const float*)d_in[4];
    const float* bq0 = (const float*)d_in[5];
    const float* Wk0 = (const float*)d_in[6];
    const float* bk0 = (const float*)d_in[7];
    const float* Wv0 = (const float*)d_in[8];
    const float* bv0 = (const float*)d_in[9];
    const float* We0 = (const float*)d_in[10];
    const float* Ws0 = (const float*)d_in[11];
    const float* bs0 = (const float*)d_in[12];

    const float* Wq1 = (const float*)d_in[13];
    const float* bq1 = (const float*)d_in[14];
    const float* Wk1 = (const float*)d_in[15];
    const float* bk1 = (const float*)d_in[16];
    const float* Wv1 = (const float*)d_in[17];
    const float* bv1 = (const float*)d_in[18];
    const float* We1 = (const float*)d_in[19];
    const float* Ws1 = (const float*)d_in[20];
    const float* bs1 = (const float*)d_in[21];

    const float* W1 = (const float*)d_in[22];
    const float* b1 = (const float*)d_in[23];
    const float* W2 = (const float*)d_in[24];
    const float* b2 = (const float*)d_in[25];
    const float* W3 = (const float*)d_in[26];
    const float* b3 = (const float*)d_in[27];

    int n = in_sizes[2];        // num nodes
    int E = in_sizes[3];        // num edges
    float* out = (float*)d_out;

    cudaFuncSetAttribute(k_gemm_mma, cudaFuncAttributeMaxDynamicSharedMemorySize, GSM_TOTAL);

    const int* src = ei;
    const int* dst = ei + E;

    int gb = (n + 63) / 64;
    int nb8 = (n + 7) / 8;
    int snb = (n + 255) / 256;       // scan blocks (<=256 required)

    // 11 launches (gemm0 at index 3 for ncu sampling)
    k_prep<<<512, 256>>>(Wq0, Wk0, Wv0, Ws0, Wq1, Wk1, Wv1, Ws1, n);
    k_hist<<<(E + 255) / 256, 256>>>(dst, E);
    k_scan1<<<snb, 256>>>(n);
    k_gemm_mma<<<gb, 256, GSM_TOTAL>>>(x, 1, 0, n, 0, bq0, bk0, bv0, bs0, nullptr);
    k_scan2<<<1, 256>>>(snb);
    k_scan3<<<snb, 256>>>(n, E);
    k_fill<<<(E + 255) / 256, 256>>>(src, dst, eattr, E);

    // ---- layer 0 edges (writes relu'd fp16 H) ----
    k_edge_fused<<<nb8, 256>>>(We0, n, 0, nullptr, nullptr, 0);

    // ---- layer 1 (A = d_Hh copy; skip+messages -> d_out; pool fused) ----
    k_gemm_mma<<<gb, 256, GSM_TOTAL>>>(nullptr, 0, 1, n, 4, bq1, bk1, bv1, bs1, out);
    k_edge_fused<<<nb8, 256>>>(We1, n, 1, out, batch, 1);

    // ---- MLP head ----
    k_mlp<<<GG, 128>>>(W1, b1, W2, b2, W3, b3, out, n);
}